// round 4
// baseline (speedup 1.0000x reference)
#include <cuda_runtime.h>
#include <cuda_bf16.h>

// Problem constants (from reference): B=4096, T=512, E=16, H=32, 4H=128
#define T_STEPS   512
#define H_UNITS   32
#define NCOL      128
#define NWARPS    4          // warps per block (128 threads)

typedef unsigned long long u64;

__device__ __forceinline__ u64 ffma2(u64 a, u64 b, u64 c) {
    u64 d;
    asm("fma.rn.f32x2 %0, %1, %2, %3;" : "=l"(d) : "l"(a), "l"(b), "l"(c));
    return d;
}
__device__ __forceinline__ u64 pack2(float lo, float hi) {
    u64 r;
    asm("mov.b64 %0, {%1, %2};" : "=l"(r) : "f"(lo), "f"(hi));
    return r;
}
__device__ __forceinline__ float hadd2(u64 v) {
    float lo, hi;
    asm("mov.b64 {%0, %1}, %2;" : "=f"(lo), "=f"(hi) : "l"(v));
    return lo + hi;
}
__device__ __forceinline__ float sigmoid_f(float x) {
    // 1/(1+e^-x): MUFU.EX2 + MUFU.RCP, ~1e-6 rel error
    return __fdividef(1.0f, 1.0f + __expf(-x));
}
__device__ __forceinline__ float tanh_f(float x) {
    // tanh(x) = 2/(1+e^-2x) - 1
    return __fdividef(2.0f, 1.0f + __expf(-2.0f * x)) - 1.0f;
}

__global__ void __launch_bounds__(NWARPS * 32)
lstm_kernel(const int* __restrict__ ids,
            const float* __restrict__ emb,
            const float* __restrict__ kernel,
            const float* __restrict__ rec_kernel,
            const float* __restrict__ w1,
            const float* __restrict__ b1,
            const float* __restrict__ w2,
            const float* __restrict__ b2,
            float* __restrict__ out)
{
    const int lane = threadIdx.x & 31;
    const int w    = threadIdx.x >> 5;
    const int b    = blockIdx.x * NWARPS + w;

    // Per-warp ping-pong h broadcast buffer
    __shared__ __align__(16) float hbuf[NWARPS][2][H_UNITS];

    // ---- Load weights into registers, packed over K-pairs --------------
    // Lane j owns gate columns {j, j+32, j+64, j+96} (Keras order i,f,c,o).
    // wi[g][p] = { kernel[2p][g*32+j],     kernel[2p+1][g*32+j]     }  (p=0..7)
    // wr[g][p] = { rec_kernel[2p][g*32+j], rec_kernel[2p+1][g*32+j] }  (p=0..15)
    u64 wi[4][8];
    u64 wr[4][16];
    #pragma unroll
    for (int g = 0; g < 4; ++g) {
        const int col = g * 32 + lane;
        #pragma unroll
        for (int p = 0; p < 8; ++p)
            wi[g][p] = pack2(__ldg(&kernel[(2 * p)     * NCOL + col]),
                             __ldg(&kernel[(2 * p + 1) * NCOL + col]));
        #pragma unroll
        for (int p = 0; p < 16; ++p)
            wr[g][p] = pack2(__ldg(&rec_kernel[(2 * p)     * NCOL + col]),
                             __ldg(&rec_kernel[(2 * p + 1) * NCOL + col]));
    }

    const int* idrow = ids + (long long)b * T_STEPS;
    int id = __ldg(idrow);                  // prefetch t=0 id
    float h = 0.0f, c = 0.0f;
    int cur = 0;
    hbuf[w][0][lane] = 0.0f;                // h_{-1} = 0 (syncwarp in loop orders this)

    const float4* emb4 = reinterpret_cast<const float4*>(emb);

    #pragma unroll 1
    for (int t = 0; t < T_STEPS; ++t) {
        // Issue embedding loads early (all lanes same addr -> broadcast)
        const float4* e4 = emb4 + ((long long)id << 2);
        float4 ea = __ldg(e4 + 0);
        float4 eb = __ldg(e4 + 1);
        float4 ec = __ldg(e4 + 2);
        float4 ed = __ldg(e4 + 3);
        if (t + 1 < T_STEPS) id = __ldg(idrow + t + 1);   // prefetch next id

        __syncwarp();   // orders STS(h, prev iter) before LDS below

        u64 acc0 = 0ull, acc1 = 0ull, acc2 = 0ull, acc3 = 0ull;

        // Recurrent: z += h @ rec_kernel  (h pairs via LDS.64 broadcast)
        const u64* hp = reinterpret_cast<const u64*>(hbuf[w][cur]);
        #pragma unroll
        for (int p = 0; p < 16; ++p) {
            u64 hh = hp[p];
            acc0 = ffma2(hh, wr[0][p], acc0);
            acc1 = ffma2(hh, wr[1][p], acc1);
            acc2 = ffma2(hh, wr[2][p], acc2);
            acc3 = ffma2(hh, wr[3][p], acc3);
        }

        // Input projection: z += e @ kernel
        u64 ep[8];
        ep[0] = pack2(ea.x, ea.y);  ep[1] = pack2(ea.z, ea.w);
        ep[2] = pack2(eb.x, eb.y);  ep[3] = pack2(eb.z, eb.w);
        ep[4] = pack2(ec.x, ec.y);  ep[5] = pack2(ec.z, ec.w);
        ep[6] = pack2(ed.x, ed.y);  ep[7] = pack2(ed.z, ed.w);
        #pragma unroll
        for (int p = 0; p < 8; ++p) {
            acc0 = ffma2(ep[p], wi[0][p], acc0);
            acc1 = ffma2(ep[p], wi[1][p], acc1);
            acc2 = ffma2(ep[p], wi[2][p], acc2);
            acc3 = ffma2(ep[p], wi[3][p], acc3);
        }

        float zi = hadd2(acc0);
        float zf = hadd2(acc1);
        float zc = hadd2(acc2);
        float zo = hadd2(acc3);

        float ig = sigmoid_f(zi);
        float fg = sigmoid_f(zf);
        float gg = tanh_f(zc);
        float og = sigmoid_f(zo);

        c = fg * c + ig * gg;
        h = og * tanh_f(c);

        cur ^= 1;
        hbuf[w][cur][lane] = h;   // publish h_t into the other buffer
    }

    // ---- MLP tail: y = relu(h @ w1 + b1) @ w2 + b2 ----------------------
    __syncwarp();
    const float* hf = hbuf[w][cur];
    float d = __ldg(&b1[lane]);
    #pragma unroll
    for (int j = 0; j < 32; ++j)
        d = fmaf(hf[j], __ldg(&w1[j * 32 + lane]), d);
    d = fmaxf(d, 0.0f);
    float v = d * __ldg(&w2[lane]);
    #pragma unroll
    for (int off = 16; off > 0; off >>= 1)
        v += __shfl_down_sync(0xffffffffu, v, off);
    if (lane == 0)
        out[b] = v + __ldg(b2);
}

extern "C" void kernel_launch(void* const* d_in, const int* in_sizes, int n_in,
                              void* d_out, int out_size)
{
    const int*   ids        = (const int*)  d_in[0];
    const float* emb        = (const float*)d_in[1];
    const float* kernel     = (const float*)d_in[2];
    const float* rec_kernel = (const float*)d_in[3];
    const float* w1         = (const float*)d_in[4];
    const float* b1         = (const float*)d_in[5];
    const float* w2         = (const float*)d_in[6];
    const float* b2         = (const float*)d_in[7];
    float*       out        = (float*)d_out;

    const int B = in_sizes[0] / T_STEPS;        // 4096
    const int blocks = (B + NWARPS - 1) / NWARPS;

    lstm_kernel<<<blocks, NWARPS * 32>>>(ids, emb, kernel, rec_kernel,
                                         w1, b1, w2, b2, out);
}

// round 5
// speedup vs baseline: 1.2674x; 1.2674x over previous
#include <cuda_runtime.h>
#include <cuda_bf16.h>

// Problem constants: B=4096, T=512, E=16, H=32, 4H=128, buckets=1000
#define T_STEPS   512
#define H_UNITS   32
#define NCOL      128
#define EMB_DIM   16
#define NWARPS    4          // warps per block (128 threads)
#define MAX_BUCKETS 1024

typedef unsigned long long u64;

// Precomputed input projection table: proj[id][j][g] = (emb[id] @ kernel)[g*32+j]
// Layout: row id -> 128 float4's? Stored as [id][j*4+g], lane j reads float4 at j.
__device__ float g_proj[MAX_BUCKETS * 512];

__device__ __forceinline__ u64 ffma2(u64 a, u64 b, u64 c) {
    u64 d;
    asm("fma.rn.f32x2 %0, %1, %2, %3;" : "=l"(d) : "l"(a), "l"(b), "l"(c));
    return d;
}
__device__ __forceinline__ u64 fadd2(u64 a, u64 b) {
    u64 d;
    asm("add.rn.f32x2 %0, %1, %2;" : "=l"(d) : "l"(a), "l"(b));
    return d;
}
__device__ __forceinline__ u64 pack2(float lo, float hi) {
    u64 r;
    asm("mov.b64 %0, {%1, %2};" : "=l"(r) : "f"(lo), "f"(hi));
    return r;
}
__device__ __forceinline__ float hadd2(u64 v) {
    float lo, hi;
    asm("mov.b64 {%0, %1}, %2;" : "=f"(lo), "=f"(hi) : "l"(v));
    return lo + hi;
}
__device__ __forceinline__ float sigmoid_f(float x) {
    return __fdividef(1.0f, 1.0f + __expf(-x));
}
__device__ __forceinline__ float tanh_f(float x) {
    return __fdividef(2.0f, 1.0f + __expf(-2.0f * x)) - 1.0f;
}

// ---------------------------------------------------------------------------
// Prologue: proj[id][j*4+g] = sum_e emb[id][e] * kernel[e][g*32+j]
// grid = n_buckets, block = 512 (one thread per output element)
// ---------------------------------------------------------------------------
__global__ void proj_kernel(const float* __restrict__ emb,
                            const float* __restrict__ kernel)
{
    const int id  = blockIdx.x;
    const int tid = threadIdx.x;            // 0..511
    const int j   = tid >> 2;               // unit
    const int g   = tid & 3;                // gate (i,f,c,o)
    const float* e = emb + id * EMB_DIM;
    float s = 0.0f;
    #pragma unroll
    for (int k = 0; k < EMB_DIM; ++k)
        s = fmaf(__ldg(&e[k]), __ldg(&kernel[k * NCOL + g * 32 + j]), s);
    g_proj[id * 512 + tid] = s;
}

// ---------------------------------------------------------------------------
// Main LSTM kernel: 1 warp = 1 batch row, lane j = hidden unit j
// ---------------------------------------------------------------------------
__global__ void __launch_bounds__(NWARPS * 32, 2)
lstm_kernel(const int* __restrict__ ids,
            const float* __restrict__ rec_kernel,
            const float* __restrict__ w1,
            const float* __restrict__ b1,
            const float* __restrict__ w2,
            const float* __restrict__ b2,
            float* __restrict__ out)
{
    const int lane = threadIdx.x & 31;
    const int w    = threadIdx.x >> 5;
    const int b    = blockIdx.x * NWARPS + w;

    __shared__ __align__(16) float hbuf[NWARPS][2][H_UNITS];

    // Recurrent weights in registers, packed over K-pairs.
    // wr[g][p] = { rec_kernel[2p][g*32+lane], rec_kernel[2p+1][g*32+lane] }
    u64 wr[4][16];
    #pragma unroll
    for (int g = 0; g < 4; ++g) {
        const int col = g * 32 + lane;
        #pragma unroll
        for (int p = 0; p < 16; ++p)
            wr[g][p] = pack2(__ldg(&rec_kernel[(2 * p)     * NCOL + col]),
                             __ldg(&rec_kernel[(2 * p + 1) * NCOL + col]));
    }

    const int* idrow = ids + (long long)b * T_STEPS;
    const float4* proj4 = reinterpret_cast<const float4*>(g_proj);

    // 2-deep prefetch pipeline for the xz table rows.
    int idA = __ldg(idrow + 0);
    int idB = __ldg(idrow + 1);
    float4 xz_cur = __ldg(proj4 + idA * 128 + lane);   // step 0
    float4 xz_nxt = __ldg(proj4 + idB * 128 + lane);   // step 1
    int id_n2 = __ldg(idrow + 2);                      // id for step 2

    float h = 0.0f, c = 0.0f;
    int cur = 0;
    hbuf[w][0][lane] = 0.0f;

    #pragma unroll 1
    for (int t = 0; t < T_STEPS; ++t) {
        // Prefetch xz for step t+2 and id for step t+3 (clamped; redundant at tail)
        float4 xz_n2 = __ldg(proj4 + id_n2 * 128 + lane);
        int t3 = t + 3; if (t3 > T_STEPS - 1) t3 = T_STEPS - 1;
        int id_n3 = __ldg(idrow + t3);

        __syncwarp();   // orders previous STS(h) before LDS below

        // Recurrent: z += h_{t-1} @ rec_kernel, two 8-deep chains per gate
        u64 a0 = 0ull, a1 = 0ull, a2 = 0ull, a3 = 0ull;
        u64 c0 = 0ull, c1 = 0ull, c2 = 0ull, c3 = 0ull;
        const u64* hp = reinterpret_cast<const u64*>(hbuf[w][cur]);
        #pragma unroll
        for (int p = 0; p < 8; ++p) {
            u64 hh = hp[p];
            a0 = ffma2(hh, wr[0][p], a0);
            a1 = ffma2(hh, wr[1][p], a1);
            a2 = ffma2(hh, wr[2][p], a2);
            a3 = ffma2(hh, wr[3][p], a3);
        }
        #pragma unroll
        for (int p = 8; p < 16; ++p) {
            u64 hh = hp[p];
            c0 = ffma2(hh, wr[0][p], c0);
            c1 = ffma2(hh, wr[1][p], c1);
            c2 = ffma2(hh, wr[2][p], c2);
            c3 = ffma2(hh, wr[3][p], c3);
        }

        float zi = hadd2(fadd2(a0, c0)) + xz_cur.x;
        float zf = hadd2(fadd2(a1, c1)) + xz_cur.y;
        float zc = hadd2(fadd2(a2, c2)) + xz_cur.z;
        float zo = hadd2(fadd2(a3, c3)) + xz_cur.w;

        float ig = sigmoid_f(zi);
        float fg = sigmoid_f(zf);
        float gg = tanh_f(zc);
        float og = sigmoid_f(zo);

        c = fg * c + ig * gg;
        h = og * tanh_f(c);

        cur ^= 1;
        hbuf[w][cur][lane] = h;

        // rotate prefetch pipeline
        xz_cur = xz_nxt;
        xz_nxt = xz_n2;
        id_n2  = id_n3;
    }

    // ---- MLP tail: y = relu(h @ w1 + b1) @ w2 + b2 ----------------------
    __syncwarp();
    const float* hf = hbuf[w][cur];
    float d = __ldg(&b1[lane]);
    #pragma unroll
    for (int j = 0; j < 32; ++j)
        d = fmaf(hf[j], __ldg(&w1[j * 32 + lane]), d);
    d = fmaxf(d, 0.0f);
    float v = d * __ldg(&w2[lane]);
    #pragma unroll
    for (int off = 16; off > 0; off >>= 1)
        v += __shfl_down_sync(0xffffffffu, v, off);
    if (lane == 0)
        out[b] = v + __ldg(b2);
}

extern "C" void kernel_launch(void* const* d_in, const int* in_sizes, int n_in,
                              void* d_out, int out_size)
{
    const int*   ids        = (const int*)  d_in[0];
    const float* emb        = (const float*)d_in[1];
    const float* kernel     = (const float*)d_in[2];
    const float* rec_kernel = (const float*)d_in[3];
    const float* w1         = (const float*)d_in[4];
    const float* b1         = (const float*)d_in[5];
    const float* w2         = (const float*)d_in[6];
    const float* b2         = (const float*)d_in[7];
    float*       out        = (float*)d_out;

    int buckets = in_sizes[1] / EMB_DIM;            // 1000
    if (buckets > MAX_BUCKETS) buckets = MAX_BUCKETS;
    proj_kernel<<<buckets, 512>>>(emb, kernel);

    const int B = in_sizes[0] / T_STEPS;            // 4096
    const int blocks = (B + NWARPS - 1) / NWARPS;
    lstm_kernel<<<blocks, NWARPS * 32>>>(ids, rec_kernel, w1, b1, w2, b2, out);
}

// round 9
// speedup vs baseline: 1.4688x; 1.1589x over previous
#include <cuda_runtime.h>
#include <cuda_bf16.h>

// Problem constants: B=4096, T=512, E=16, H=32, 4H=128, buckets=1000
#define T_STEPS     512
#define H_UNITS     32
#define NCOL        128
#define EMB_DIM     16
#define NWARPS      4          // warps per block (128 threads)
#define ROWS_PER_W  2          // batch rows per warp
#define MAX_BUCKETS 1024

typedef unsigned long long u64;

// Precomputed input projection: proj[id][j*4+g] = (emb[id] @ kernel)[g*32+j]
// Lane j reads float4 at [id*128 + j] -> (zi, zf, zc, zo) contributions.
__device__ float g_proj[MAX_BUCKETS * 512];

__device__ __forceinline__ u64 ffma2(u64 a, u64 b, u64 c) {
    u64 d;
    asm("fma.rn.f32x2 %0, %1, %2, %3;" : "=l"(d) : "l"(a), "l"(b), "l"(c));
    return d;
}
__device__ __forceinline__ u64 pack2(float lo, float hi) {
    u64 r;
    asm("mov.b64 %0, {%1, %2};" : "=l"(r) : "f"(lo), "f"(hi));
    return r;
}
__device__ __forceinline__ float hadd2(u64 v) {
    float lo, hi;
    asm("mov.b64 {%0, %1}, %2;" : "=f"(lo), "=f"(hi) : "l"(v));
    return lo + hi;
}
__device__ __forceinline__ float tanh_fast(float x) {
    float y;
    asm("tanh.approx.f32 %0, %1;" : "=f"(y) : "f"(x));
    return y;
}
__device__ __forceinline__ float sigmoid_fast(float x) {
    return fmaf(0.5f, tanh_fast(0.5f * x), 0.5f);
}

// ---------------------------------------------------------------------------
// Prologue: proj[id][j*4+g] = sum_e emb[id][e] * kernel[e][g*32+j]
// ---------------------------------------------------------------------------
__global__ void proj_kernel(const float* __restrict__ emb,
                            const float* __restrict__ kernel)
{
    const int id  = blockIdx.x;
    const int tid = threadIdx.x;            // 0..511
    const int j   = tid >> 2;               // unit
    const int g   = tid & 3;                // gate (i,f,c,o)
    const float* e = emb + id * EMB_DIM;
    float s = 0.0f;
    #pragma unroll
    for (int k = 0; k < EMB_DIM; ++k)
        s = fmaf(__ldg(&e[k]), __ldg(&kernel[k * NCOL + g * 32 + j]), s);
    g_proj[id * 512 + tid] = s;
}

// ---------------------------------------------------------------------------
// Main LSTM kernel: 1 warp = 2 batch rows, lane j = hidden unit j
// ---------------------------------------------------------------------------
__global__ void __launch_bounds__(NWARPS * 32, 2)
lstm_kernel(const int* __restrict__ ids,
            const float* __restrict__ rec_kernel,
            const float* __restrict__ w1,
            const float* __restrict__ b1,
            const float* __restrict__ w2,
            const float* __restrict__ b2,
            float* __restrict__ out)
{
    const int lane = threadIdx.x & 31;
    const int w    = threadIdx.x >> 5;
    const int b0   = (blockIdx.x * NWARPS + w) * ROWS_PER_W;  // rows b0, b0+1

    // [warp][row][pingpong][unit]
    __shared__ __align__(16) float hbuf[NWARPS][ROWS_PER_W][2][H_UNITS];

    // Recurrent weights, packed over K-pairs, shared by both rows.
    // wr[g][p] = { rec_kernel[2p][g*32+lane], rec_kernel[2p+1][g*32+lane] }
    u64 wr[4][16];
    #pragma unroll
    for (int g = 0; g < 4; ++g) {
        const int col = g * 32 + lane;
        #pragma unroll
        for (int p = 0; p < 16; ++p)
            wr[g][p] = pack2(__ldg(&rec_kernel[(2 * p)     * NCOL + col]),
                             __ldg(&rec_kernel[(2 * p + 1) * NCOL + col]));
    }

    const int* idrow0 = ids + (long long)b0 * T_STEPS;
    const int* idrow1 = idrow0 + T_STEPS;
    const float4* proj4 = reinterpret_cast<const float4*>(g_proj);

    // 2-deep prefetch pipeline per row.
    float4 xzc0 = __ldg(proj4 + __ldg(idrow0 + 0) * 128 + lane);
    float4 xzc1 = __ldg(proj4 + __ldg(idrow1 + 0) * 128 + lane);
    float4 xzn0 = __ldg(proj4 + __ldg(idrow0 + 1) * 128 + lane);
    float4 xzn1 = __ldg(proj4 + __ldg(idrow1 + 1) * 128 + lane);
    int id2_0 = __ldg(idrow0 + 2);
    int id2_1 = __ldg(idrow1 + 2);

    float h0 = 0.0f, c0v = 0.0f, h1 = 0.0f, c1v = 0.0f;
    int cur = 0;
    hbuf[w][0][0][lane] = 0.0f;
    hbuf[w][1][0][lane] = 0.0f;

    #pragma unroll 1
    for (int t = 0; t < T_STEPS; ++t) {
        // Prefetch xz for step t+2, ids for step t+3 (clamped at tail)
        float4 xz2_0 = __ldg(proj4 + id2_0 * 128 + lane);
        float4 xz2_1 = __ldg(proj4 + id2_1 * 128 + lane);
        int t3 = t + 3; if (t3 > T_STEPS - 1) t3 = T_STEPS - 1;
        int id3_0 = __ldg(idrow0 + t3);
        int id3_1 = __ldg(idrow1 + t3);

        __syncwarp();   // orders previous STS(h) before LDS below

        // Accumulators seeded with the input projection: acc = {xz, 0}
        u64 A0 = pack2(xzc0.x, 0.0f), A1 = pack2(xzc0.y, 0.0f);
        u64 A2 = pack2(xzc0.z, 0.0f), A3 = pack2(xzc0.w, 0.0f);
        u64 B0 = pack2(xzc1.x, 0.0f), B1 = pack2(xzc1.y, 0.0f);
        u64 B2 = pack2(xzc1.z, 0.0f), B3 = pack2(xzc1.w, 0.0f);

        const u64* hp0 = reinterpret_cast<const u64*>(hbuf[w][0][cur]);
        const u64* hp1 = reinterpret_cast<const u64*>(hbuf[w][1][cur]);
        #pragma unroll
        for (int p = 0; p < 16; ++p) {
            u64 ha = hp0[p];
            u64 hb = hp1[p];
            A0 = ffma2(ha, wr[0][p], A0);   B0 = ffma2(hb, wr[0][p], B0);
            A1 = ffma2(ha, wr[1][p], A1);   B1 = ffma2(hb, wr[1][p], B1);
            A2 = ffma2(ha, wr[2][p], A2);   B2 = ffma2(hb, wr[2][p], B2);
            A3 = ffma2(ha, wr[3][p], A3);   B3 = ffma2(hb, wr[3][p], B3);
        }

        // Row 0 gates
        {
            float zi = hadd2(A0), zf = hadd2(A1), zc = hadd2(A2), zo = hadd2(A3);
            float ig = sigmoid_fast(zi);
            float fg = sigmoid_fast(zf);
            float gg = tanh_fast(zc);
            float og = sigmoid_fast(zo);
            c0v = fmaf(fg, c0v, ig * gg);
            h0  = og * tanh_fast(c0v);
        }
        // Row 1 gates
        {
            float zi = hadd2(B0), zf = hadd2(B1), zc = hadd2(B2), zo = hadd2(B3);
            float ig = sigmoid_fast(zi);
            float fg = sigmoid_fast(zf);
            float gg = tanh_fast(zc);
            float og = sigmoid_fast(zo);
            c1v = fmaf(fg, c1v, ig * gg);
            h1  = og * tanh_fast(c1v);
        }

        cur ^= 1;
        hbuf[w][0][cur][lane] = h0;
        hbuf[w][1][cur][lane] = h1;

        // rotate prefetch pipeline
        xzc0 = xzn0;  xzn0 = xz2_0;  id2_0 = id3_0;
        xzc1 = xzn1;  xzn1 = xz2_1;  id2_1 = id3_1;
    }

    // ---- MLP tail: y = relu(h @ w1 + b1) @ w2 + b2, for both rows -------
    __syncwarp();
    #pragma unroll
    for (int r = 0; r < ROWS_PER_W; ++r) {
        const float* hf = hbuf[w][r][cur];
        float d = __ldg(&b1[lane]);
        #pragma unroll
        for (int j = 0; j < 32; ++j)
            d = fmaf(hf[j], __ldg(&w1[j * 32 + lane]), d);
        d = fmaxf(d, 0.0f);
        float v = d * __ldg(&w2[lane]);
        #pragma unroll
        for (int off = 16; off > 0; off >>= 1)
            v += __shfl_down_sync(0xffffffffu, v, off);
        if (lane == 0)
            out[b0 + r] = v + __ldg(b2);
    }
}

extern "C" void kernel_launch(void* const* d_in, const int* in_sizes, int n_in,
                              void* d_out, int out_size)
{
    const int*   ids        = (const int*)  d_in[0];
    const float* emb        = (const float*)d_in[1];
    const float* kernel     = (const float*)d_in[2];
    const float* rec_kernel = (const float*)d_in[3];
    const float* w1         = (const float*)d_in[4];
    const float* b1         = (const float*)d_in[5];
    const float* w2         = (const float*)d_in[6];
    const float* b2         = (const float*)d_in[7];
    float*       out        = (float*)d_out;

    int buckets = in_sizes[1] / EMB_DIM;            // 1000
    if (buckets > MAX_BUCKETS) buckets = MAX_BUCKETS;
    proj_kernel<<<buckets, 512>>>(emb, kernel);

    const int B = in_sizes[0] / T_STEPS;            // 4096
    const int rows_per_block = NWARPS * ROWS_PER_W; // 8
    const int blocks = (B + rows_per_block - 1) / rows_per_block;
    lstm_kernel<<<blocks, NWARPS * 32>>>(ids, rec_kernel, w1, b1, w2, b2, out);
}